// round 4
// baseline (speedup 1.0000x reference)
#include <cuda_runtime.h>
#include <cstdint>
#include <cstddef>

#define NB 8
#define NL 4096
#define ND 1024
#define NROWS (NB*NL)   // 32768

// ---- scratch (device globals; no allocation allowed) ----
__device__ float g_Q[(size_t)NROWS * ND];
__device__ float g_K[(size_t)NROWS * ND];
__device__ float g_V[(size_t)NROWS * ND];    // becomes U (=T@Vb) in place
__device__ float g_O[(size_t)NROWS * ND];
__device__ float g_Wt[(size_t)NROWS * ND];   // W^T per chunk: [b*64+n][kdim][64]
__device__ float g_Qt[(size_t)NROWS * ND];   // Q^T per chunk: [b*64+n][kdim][64]
__device__ float g_beta[NROWS];
__device__ float g_A[(size_t)NB * 64 * 64 * 64];

__device__ __forceinline__ uint32_t f2tf32(float x) {
    uint32_t r;
    asm("cvt.rna.tf32.f32 %0, %1;" : "=r"(r) : "f"(x));
    return r;
}

// =====================================================================
// tf32 mma.sync GEMM: C(MxN) = A(MxK) @ W(NxK)^T + bias(N)   (as R3)
// =====================================================================
#define GPITCH 36
#define GASZ   (128 * GPITCH)
#define GSMEM  (4 * GASZ * 4)

__global__ void __launch_bounds__(256, 1) gemm_mma(
    const float* __restrict__ A, const float* __restrict__ Wm,
    const float* __restrict__ bias, float* __restrict__ C,
    int M, int N, int K)
{
    extern __shared__ uint32_t smg[];
    const int t    = threadIdx.x;
    const int wid  = t >> 5;
    const int lane = t & 31;
    const int wm   = wid & 1;
    const int wn   = wid >> 1;
    const int m0   = blockIdx.y * 128;
    const int n0   = blockIdx.x * 128;
    const int lr   = lane >> 2;
    const int lc   = lane & 3;

    const float* Ap = A  + (size_t)m0 * K;
    const float* Bp = Wm + (size_t)n0 * K;

    float acc[4][4][4];
#pragma unroll
    for (int i = 0; i < 4; i++)
#pragma unroll
        for (int j = 0; j < 4; j++)
#pragma unroll
            for (int x = 0; x < 4; x++) acc[i][j][x] = 0.f;

#pragma unroll
    for (int i = 0; i < 4; i++) {
        int idx = t + i * 256;
        int r = idx >> 3, c4 = idx & 7;
        float4 va = *(const float4*)(Ap + (size_t)r * K + c4 * 4);
        uint32_t* dst = &smg[r * GPITCH + c4 * 4];
        dst[0] = f2tf32(va.x); dst[1] = f2tf32(va.y);
        dst[2] = f2tf32(va.z); dst[3] = f2tf32(va.w);
        float4 vb = *(const float4*)(Bp + (size_t)r * K + c4 * 4);
        uint32_t* dstb = &smg[GASZ + r * GPITCH + c4 * 4];
        dstb[0] = f2tf32(vb.x); dstb[1] = f2tf32(vb.y);
        dstb[2] = f2tf32(vb.z); dstb[3] = f2tf32(vb.w);
    }
    __syncthreads();

    const int nkt = K >> 5;
    for (int kt = 0; kt < nkt; kt++) {
        const int cur = kt & 1;
        float4 ra[4], rb[4];
        if (kt + 1 < nkt) {
            const int ko = (kt + 1) * 32;
#pragma unroll
            for (int i = 0; i < 4; i++) {
                int idx = t + i * 256;
                int r = idx >> 3, c4 = idx & 7;
                ra[i] = *(const float4*)(Ap + (size_t)r * K + ko + c4 * 4);
                rb[i] = *(const float4*)(Bp + (size_t)r * K + ko + c4 * 4);
            }
        }
        const uint32_t* As = smg + cur * 2 * GASZ;
        const uint32_t* Bs = As + GASZ;
#pragma unroll
        for (int k8 = 0; k8 < 4; k8++) {
            const int kb = k8 * 8 + lc;
            uint32_t af[4][4], bf[4][2];
#pragma unroll
            for (int mt = 0; mt < 4; mt++) {
                int r = wm * 64 + mt * 16 + lr;
                af[mt][0] = As[r * GPITCH + kb];
                af[mt][1] = As[(r + 8) * GPITCH + kb];
                af[mt][2] = As[r * GPITCH + kb + 4];
                af[mt][3] = As[(r + 8) * GPITCH + kb + 4];
            }
#pragma unroll
            for (int nt = 0; nt < 4; nt++) {
                int n = wn * 32 + nt * 8 + lr;
                bf[nt][0] = Bs[n * GPITCH + kb];
                bf[nt][1] = Bs[n * GPITCH + kb + 4];
            }
#pragma unroll
            for (int mt = 0; mt < 4; mt++)
#pragma unroll
                for (int nt = 0; nt < 4; nt++) {
                    asm volatile(
                        "mma.sync.aligned.m16n8k8.row.col.f32.tf32.tf32.f32 "
                        "{%0,%1,%2,%3}, {%4,%5,%6,%7}, {%8,%9}, {%0,%1,%2,%3};"
                        : "+f"(acc[mt][nt][0]), "+f"(acc[mt][nt][1]),
                          "+f"(acc[mt][nt][2]), "+f"(acc[mt][nt][3])
                        : "r"(af[mt][0]), "r"(af[mt][1]), "r"(af[mt][2]), "r"(af[mt][3]),
                          "r"(bf[nt][0]), "r"(bf[nt][1]));
                }
        }
        if (kt + 1 < nkt) {
            uint32_t* dA = smg + (1 - cur) * 2 * GASZ;
            uint32_t* dB = dA + GASZ;
#pragma unroll
            for (int i = 0; i < 4; i++) {
                int idx = t + i * 256;
                int r = idx >> 3, c4 = idx & 7;
                uint32_t* da = &dA[r * GPITCH + c4 * 4];
                da[0] = f2tf32(ra[i].x); da[1] = f2tf32(ra[i].y);
                da[2] = f2tf32(ra[i].z); da[3] = f2tf32(ra[i].w);
                uint32_t* db = &dB[r * GPITCH + c4 * 4];
                db[0] = f2tf32(rb[i].x); db[1] = f2tf32(rb[i].y);
                db[2] = f2tf32(rb[i].z); db[3] = f2tf32(rb[i].w);
            }
        }
        __syncthreads();
    }

#pragma unroll
    for (int mt = 0; mt < 4; mt++) {
        int r = m0 + wm * 64 + mt * 16 + lr;
#pragma unroll
        for (int nt = 0; nt < 4; nt++) {
            int c = n0 + wn * 32 + nt * 8 + 2 * lc;
            float2 bv = *(const float2*)&bias[c];
            float2 o0, o1;
            o0.x = acc[mt][nt][0] + bv.x; o0.y = acc[mt][nt][1] + bv.y;
            o1.x = acc[mt][nt][2] + bv.x; o1.y = acc[mt][nt][3] + bv.y;
            *(float2*)&C[(size_t)r * N + c]       = o0;
            *(float2*)&C[(size_t)(r + 8) * N + c] = o1;
        }
    }
}

// =====================================================================
// beta[row] = 1 / (||K_row||^2 + 1e-6)
// =====================================================================
__global__ void __launch_bounds__(256) beta_kernel()
{
    int row  = blockIdx.x * 8 + (threadIdx.x >> 5);
    int lane = threadIdx.x & 31;
    const float* p = g_K + (size_t)row * ND;
    float s = 0.f;
#pragma unroll
    for (int i = 0; i < 8; i++) {
        float4 v = *(const float4*)&p[lane * 4 + i * 128];
        s += v.x * v.x + v.y * v.y + v.z * v.z + v.w * v.w;
    }
#pragma unroll
    for (int o = 16; o; o >>= 1) s += __shfl_xor_sync(0xffffffffu, s, o);
    if (lane == 0) g_beta[row] = 1.f / (s + 1e-6f);
}

// =====================================================================
// prep: per (batch, chunk) block; also writes Q^T and W^T chunk tiles
// =====================================================================
#define PPAD 35
__global__ void __launch_bounds__(256) prep_kernel()
{
    __shared__ float sA[64 * PPAD];
    __shared__ float sB[64 * PPAD];
    __shared__ float T_s[64 * 64];
    __shared__ float rowtmp[64];
    __shared__ float beta_s[64];

    const int t  = threadIdx.x;
    const int bc = blockIdx.x;
    const size_t row0 = (size_t)(bc >> 6) * NL + (size_t)(bc & 63) * 64;
    const size_t tb   = (size_t)bc * 65536;   // transposed chunk base

    if (t < 64) beta_s[t] = g_beta[row0 + t];
    __syncthreads();

    const int i0  = (t >> 4) * 4;
    const int j0  = (t & 15) * 4;
    const int lkk = t & 31, ljr = t >> 5;
    const int tj  = t & 63;               // transpose write: row
    const int tk0 = (t >> 6) * 8;         // transpose write: col base

    float ga[4][4], qa[4][4];
#pragma unroll
    for (int a = 0; a < 4; a++)
#pragma unroll
        for (int b = 0; b < 4; b++) { ga[a][b] = 0.f; qa[a][b] = 0.f; }

    for (int k0 = 0; k0 < ND; k0 += 32) {
#pragma unroll
        for (int h = 0; h < 8; h++) {
            int j = ljr + h * 8;
            sA[j * PPAD + lkk] = g_K[(row0 + j) * ND + k0 + lkk];
            sB[j * PPAD + lkk] = g_Q[(row0 + j) * ND + k0 + lkk];
        }
        __syncthreads();
        // write Q^T tile (coalesced; reads sB, no hazard with FMA reads)
#pragma unroll
        for (int h = 0; h < 8; h++) {
            int kk = tk0 + h;
            g_Qt[tb + (size_t)(k0 + kk) * 64 + tj] = sB[tj * PPAD + kk];
        }
#pragma unroll
        for (int kk = 0; kk < 32; kk++) {
            float ki[4], kj[4], qi[4];
#pragma unroll
            for (int a = 0; a < 4; a++) {
                ki[a] = sA[(i0 + a) * PPAD + kk];
                qi[a] = sB[(i0 + a) * PPAD + kk];
                kj[a] = sA[(j0 + a) * PPAD + kk];
            }
#pragma unroll
            for (int a = 0; a < 4; a++)
#pragma unroll
                for (int b = 0; b < 4; b++) {
                    ga[a][b] += ki[a] * kj[b];
                    qa[a][b] += qi[a] * kj[b];
                }
        }
        __syncthreads();
    }

    float* Aout = g_A + (size_t)bc * 4096;
#pragma unroll
    for (int a = 0; a < 4; a++)
#pragma unroll
        for (int b = 0; b < 4; b++) {
            int i = i0 + a, j = j0 + b;
            T_s[i * 64 + j]  = (j < i) ? (-beta_s[i] * ga[a][b]) : 0.f;
            Aout[i * 64 + j] = (j <= i) ? qa[a][b] : 0.f;
        }
    __syncthreads();

    for (int i = 1; i < 64; i++) {
        if (t < i) rowtmp[t] = T_s[i * 64 + t];
        __syncthreads();
        if (t < i) {
            float s = 0.f;
            for (int j = t + 1; j < i; j++) s += rowtmp[j] * T_s[j * 64 + t];
            T_s[i * 64 + t] += s;
        }
        __syncthreads();
    }
    if (t < 64) T_s[t * 64 + t] += 1.f;
    __syncthreads();

    const int ip = (t >> 4) * 4;
    const int dp = (t & 15) * 2;
    for (int d0 = 0; d0 < ND; d0 += 32) {
#pragma unroll
        for (int h = 0; h < 8; h++) {
            int j = ljr + h * 8;
            float bj = beta_s[j];
            sA[j * PPAD + lkk] = g_K[(row0 + j) * ND + d0 + lkk] * bj;
            sB[j * PPAD + lkk] = g_V[(row0 + j) * ND + d0 + lkk] * bj;
        }
        __syncthreads();
        float wv[4][2], uv[4][2];
#pragma unroll
        for (int a = 0; a < 4; a++) { wv[a][0] = wv[a][1] = 0.f; uv[a][0] = uv[a][1] = 0.f; }
#pragma unroll
        for (int j = 0; j < 64; j++) {
            float kb0 = sA[j * PPAD + dp], kb1 = sA[j * PPAD + dp + 1];
            float vb0 = sB[j * PPAD + dp], vb1 = sB[j * PPAD + dp + 1];
#pragma unroll
            for (int a = 0; a < 4; a++) {
                float tv = T_s[(ip + a) * 64 + j];
                wv[a][0] += tv * kb0; wv[a][1] += tv * kb1;
                uv[a][0] += tv * vb0; uv[a][1] += tv * vb1;
            }
        }
        // U -> g_V (in place)
#pragma unroll
        for (int a = 0; a < 4; a++) {
            size_t off = (row0 + ip + a) * ND + d0 + dp;
            *(float2*)&g_V[off] = make_float2(uv[a][0], uv[a][1]);
        }
        __syncthreads();   // everyone done reading sA
        // stash W window into sA, then write W^T coalesced
#pragma unroll
        for (int a = 0; a < 4; a++) {
            sA[(ip + a) * PPAD + dp]     = wv[a][0];
            sA[(ip + a) * PPAD + dp + 1] = wv[a][1];
        }
        __syncthreads();
#pragma unroll
        for (int h = 0; h < 8; h++) {
            int dd = tk0 + h;
            g_Wt[tb + (size_t)(d0 + dd) * 64 + tj] = sA[tj * PPAD + dd];
        }
        __syncthreads();
    }
}

// =====================================================================
// scan v2: grid (32 colblocks, 8 batches), 256 thr.
// S (1024x32) resident in smem (pitch 36) across 64 chunks.
// phase b: 4-way k-split in registers, W^T/Q^T direct LDG.128.
// phase d: 4 kdim passes, K direct LDG.128, dS register tiles.
// =====================================================================
#define SPAD   36
#define UPITCH 36
// floats: Ss + u_s + qs_s + A_s(64*65) + P1 + P2 (each 2*64*36)
#define SCAN_FLOATS (1024*SPAD + 64*UPITCH + 64*UPITCH + 64*65 + 2*2*64*36)
#define SCAN_SMEM   (SCAN_FLOATS * 4)

__global__ void __launch_bounds__(256, 1) scan_kernel()
{
    extern __shared__ float smn[];
    float* Ss   = smn;                       // [1024][36]
    float* u_s  = Ss + 1024 * SPAD;          // [64][36]
    float* qs_s = u_s + 64 * UPITCH;         // [64][36]
    float* A_s  = qs_s + 64 * UPITCH;        // [64][65]
    float* P1   = A_s + 64 * 65;             // [2][64][36]
    float* P2   = P1 + 2 * 64 * 36;          // [2][64][36]

    const int t   = threadIdx.x;
    const int b   = blockIdx.y;
    const int cb0 = blockIdx.x * 32;

    const int g  = t >> 6;        // k-split group 0..3
    const int t6 = t & 63;
    const int r4 = (t6 >> 2) * 4; // rows r4..r4+3
    const int c8 = (t6 & 3) * 8;  // cols c8..c8+7

    const int cr  = t >> 2;       // phase c row 0..63
    const int cc8 = (t & 3) * 8;  // phase c cols
    const int dk4 = (t >> 2) * 4; // phase d kdim offset within pass
    const int dc8 = (t & 3) * 8;  // phase d cols

    for (int i = t; i < 1024 * SPAD; i += 256) Ss[i] = 0.f;
    __syncthreads();

    for (int n = 0; n < 64; n++) {
        const size_t row0  = (size_t)b * NL + (size_t)n * 64;
        const size_t cbase = (size_t)b * 64 + n;

        // A_s load (pitch 65)
        {
            const float* Ab = g_A + cbase * 4096;
#pragma unroll
            for (int i = 0; i < 16; i++) {
                int idx = t + i * 256;
                A_s[(idx >> 6) * 65 + (idx & 63)] = Ab[idx];
            }
        }

        // ---- phase b: ua = [g==0]*U0 - W@S (partial), qa = Q@S (partial) ----
        float ua[4][8], qa[4][8];
#pragma unroll
        for (int rr = 0; rr < 4; rr++) {
            if (g == 0) {
                float4 v0 = *(const float4*)&g_V[(row0 + r4 + rr) * ND + cb0 + c8];
                float4 v1 = *(const float4*)&g_V[(row0 + r4 + rr) * ND + cb0 + c8 + 4];
                ua[rr][0] = v0.x; ua[rr][1] = v0.y; ua[rr][2] = v0.z; ua[rr][3] = v0.w;
                ua[rr][4] = v1.x; ua[rr][5] = v1.y; ua[rr][6] = v1.z; ua[rr][7] = v1.w;
            } else {
#pragma unroll
                for (int x = 0; x < 8; x++) ua[rr][x] = 0.f;
            }
#pragma unroll
            for (int x = 0; x < 8; x++) qa[rr][x] = 0.f;
        }
        {
            const float* wtp = g_Wt + (cbase * 1024 + (size_t)g * 256) * 64 + r4;
            const float* qtp = g_Qt + (cbase * 1024 + (size_t)g * 256) * 64 + r4;
            const float* ssp = Ss + (g * 256) * SPAD + c8;

            float4 w4 = *(const float4*)wtp;
            float4 q4 = *(const float4*)qtp;
            float4 s0 = *(const float4*)ssp;
            float4 s1 = *(const float4*)(ssp + 4);
#pragma unroll 2
            for (int kk = 0; kk < 256; kk++) {
                float4 wc = w4, qc = q4, sc0 = s0, sc1 = s1;
                if (kk < 255) {
                    w4 = *(const float4*)(wtp + (kk + 1) * 64);
                    q4 = *(const float4*)(qtp + (kk + 1) * 64);
                    s0 = *(const float4*)(ssp + (kk + 1) * SPAD);
                    s1 = *(const float4*)(ssp + (kk + 1) * SPAD + 4);
                }
                float sv[8] = {sc0.x, sc0.y, sc0.z, sc0.w, sc1.x, sc1.y, sc1.z, sc1.w};
                float wv[4] = {wc.x, wc.y, wc.z, wc.w};
                float qv[4] = {qc.x, qc.y, qc.z, qc.w};
#pragma unroll
                for (int rr = 0; rr < 4; rr++)
#pragma unroll
                    for (int x = 0; x < 8; x++) {
                        ua[rr][x] -= wv[rr] * sv[x];
                        qa[rr][x] += qv[rr] * sv[x];
                    }
            }
        }

        // ---- reduce 4 partials -> u_s, qs_s ----
        if (g == 1 || g == 3) {
            float* P = (g == 1) ? P1 : P2;
#pragma unroll
            for (int rr = 0; rr < 4; rr++) {
                *(float4*)&P[(r4 + rr) * 36 + c8] =
                    make_float4(ua[rr][0], ua[rr][1], ua[rr][2], ua[rr][3]);
                *(float4*)&P[(r4 + rr) * 36 + c8 + 4] =
                    make_float4(ua[rr][4], ua[rr][5], ua[rr][6], ua[rr][7]);
                *(float4*)&P[2304 + (r4 + rr) * 36 + c8] =
                    make_float4(qa[rr][0], qa[rr][1], qa[rr][2], qa[rr][3]);
                *(float4*)&P[2304 + (r4 + rr) * 36 + c8 + 4] =
                    make_float4(qa[rr][4], qa[rr][5], qa[rr][6], qa[rr][7]);
            }
        }
        __syncthreads();
        if (g == 0 || g == 2) {
            float* P = (g == 0) ? P1 : P2;
#pragma unroll
            for (int rr = 0; rr < 4; rr++) {
                float4 a0 = *(const float4*)&P[(r4 + rr) * 36 + c8];
                float4 a1 = *(const float4*)&P[(r4 + rr) * 36 + c8 + 4];
                float4 b0 = *(const float4*)&P[2304 + (r4 + rr) * 36 + c8];
                float4 b1 = *(const float4*)&P[2304 + (r4 + rr) * 36 + c8 + 4];
                ua[rr][0] += a0.x; ua[rr][1] += a0.y; ua[rr][2] += a0.z; ua[rr][3] += a0.w;
                ua[rr][4] += a1.x; ua[rr][5] += a1.y; ua[rr][6] += a1.z; ua[rr][7] += a1.w;
                qa[rr][0] += b0.x; qa[rr][1] += b0.y; qa[rr][2] += b0.z; qa[rr][3] += b0.w;
                qa[rr][4] += b1.x; qa[rr][5] += b1.y; qa[rr][6] += b1.z; qa[rr][7] += b1.w;
            }
            if (g == 2) {
#pragma unroll
                for (int rr = 0; rr < 4; rr++) {
                    *(float4*)&P2[(r4 + rr) * 36 + c8] =
                        make_float4(ua[rr][0], ua[rr][1], ua[rr][2], ua[rr][3]);
                    *(float4*)&P2[(r4 + rr) * 36 + c8 + 4] =
                        make_float4(ua[rr][4], ua[rr][5], ua[rr][6], ua[rr][7]);
                    *(float4*)&P2[2304 + (r4 + rr) * 36 + c8] =
                        make_float4(qa[rr][0], qa[rr][1], qa[rr][2], qa[rr][3]);
                    *(float4*)&P2[2304 + (r4 + rr) * 36 + c8 + 4] =
                        make_float4(qa[rr][4], qa[rr][5], qa[rr][6], qa[rr][7]);
                }
            }
        }
        __syncthreads();
        if (g == 0) {
#pragma unroll
            for (int rr = 0; rr < 4; rr++) {
                float4 a0 = *(const float4*)&P2[(r4 + rr) * 36 + c8];
                float4 a1 = *(const float4*)&P2[(r4 + rr) * 36 + c8 + 4];
                float4 b0 = *(const float4*)&P2[2304 + (r4 + rr) * 36 + c8];
                float4 b1 = *(const float4*)&P2[2304 + (r4 + rr) * 36 + c8 + 4];
                *(float4*)&u_s[(r4 + rr) * UPITCH + c8] =
                    make_float4(ua[rr][0] + a0.x, ua[rr][1] + a0.y,
                                ua[rr][2] + a0.z, ua[rr][3] + a0.w);
                *(float4*)&u_s[(r4 + rr) * UPITCH + c8 + 4] =
                    make_float4(ua[rr][4] + a1.x, ua[rr][5] + a1.y,
                                ua[rr][6] + a1.z, ua[rr][7] + a1.w);
                *(float4*)&qs_s[(r4 + rr) * UPITCH + c8] =
                    make_float4(qa[rr][0] + b0.x, qa[rr][1] + b0.y,
                                qa[rr][2] + b0.z, qa[rr][3] + b0.w);
                *(float4*)&qs_s[(r4 + rr) * UPITCH + c8 + 4] =
                    make_float4(qa[rr][4] + b1.x, qa[rr][5] + b1.y,
                                qa[rr][6] + b1.z, qa[rr][7] + b1.w);
            }
        }
        __syncthreads();

        // ---- phase c: o = A@u + qs ----
        {
            float oa[8];
            float4 q0 = *(const float4*)&qs_s[cr * UPITCH + cc8];
            float4 q1 = *(const float4*)&qs_s[cr * UPITCH + cc8 + 4];
            oa[0] = q0.x; oa[1] = q0.y; oa[2] = q0.z; oa[3] = q0.w;
            oa[4] = q1.x; oa[5] = q1.y; oa[6] = q1.z; oa[7] = q1.w;
#pragma unroll 4
            for (int j = 0; j < 64; j++) {
                float a = A_s[cr * 65 + j];
                float4 u0 = *(const float4*)&u_s[j * UPITCH + cc8];
                float4 u1 = *(const float4*)&u_s[j * UPITCH + cc8 + 4];
                oa[0] += a * u0.x; oa[1] += a * u0.y; oa[2] += a * u0.z; oa[3] += a * u0.w;
                oa[4] += a * u1.x; oa[5] += a * u1.y; oa[6] += a * u1.z; oa[7] += a * u1.w;
            }
            *(float4*)&g_O[(row0 + cr) * ND + cb0 + cc8] =
                make_float4(oa[0], oa[1], oa[2], oa[3]);
            *(float4*)&g_O[(row0 + cr) * ND + cb0 + cc8 + 4] =
                make_float4(oa[4], oa[5], oa[6], oa[7]);
        }

        // ---- phase d: S += K^T @ u  (4 kdim passes) ----
        for (int p = 0; p < 4; p++) {
            const int kidx = p * 256 + dk4;
            float ds[4][8];
#pragma unroll
            for (int i = 0; i < 4; i++)
#pragma unroll
                for (int x = 0; x < 8; x++) ds[i][x] = 0.f;
#pragma unroll 2
            for (int j = 0; j < 64; j++) {
                float4 kv = *(const float4*)&g_K[(row0 + j) * ND + kidx];
                float4 u0 = *(const float4*)&u_s[j * UPITCH + dc8];
                float4 u1 = *(const float4*)&u_s[j * UPITCH + dc8 + 4];
                float kvv[4] = {kv.x, kv.y, kv.z, kv.w};
                float uv[8]  = {u0.x, u0.y, u0.z, u0.w, u1.x, u1.y, u1.z, u1.w};
#pragma unroll
                for (int i = 0; i < 4; i++)
#pragma unroll
                    for (int x = 0; x < 8; x++) ds[i][x] += kvv[i] * uv[x];
            }
#pragma unroll
            for (int i = 0; i < 4; i++) {
                float* sp = &Ss[(kidx + i) * SPAD + dc8];
                float4 s0 = *(const float4*)sp;
                float4 s1 = *(const float4*)(sp + 4);
                s0.x += ds[i][0]; s0.y += ds[i][1]; s0.z += ds[i][2]; s0.w += ds[i][3];
                s1.x += ds[i][4]; s1.y += ds[i][5]; s1.z += ds[i][6]; s1.w += ds[i][7];
                *(float4*)sp = s0;
                *(float4*)(sp + 4) = s1;
            }
        }
        __syncthreads();
    }
}

// =====================================================================
extern "C" void kernel_launch(void* const* d_in, const int* in_sizes, int n_in,
                              void* d_out, int out_size)
{
    int base = 1;
    if (n_in >= 10 && in_sizes[1] == 1) base = 2;
    const float* X    = (const float*)d_in[0];
    const float* Wq_w = (const float*)d_in[base + 0];
    const float* Wq_b = (const float*)d_in[base + 1];
    const float* Wk_w = (const float*)d_in[base + 2];
    const float* Wk_b = (const float*)d_in[base + 3];
    const float* Wv_w = (const float*)d_in[base + 4];
    const float* Wv_b = (const float*)d_in[base + 5];
    const float* Wo_w = (const float*)d_in[base + 6];
    const float* Wo_b = (const float*)d_in[base + 7];
    float* out = (float*)d_out;

    float *pQ, *pK, *pV, *pO;
    cudaGetSymbolAddress((void**)&pQ, g_Q);
    cudaGetSymbolAddress((void**)&pK, g_K);
    cudaGetSymbolAddress((void**)&pV, g_V);
    cudaGetSymbolAddress((void**)&pO, g_O);

    cudaFuncSetAttribute(gemm_mma, cudaFuncAttributeMaxDynamicSharedMemorySize, GSMEM);
    dim3 gg(ND / 128, NROWS / 128);
    gemm_mma<<<gg, 256, GSMEM>>>(X, Wq_w, Wq_b, pQ, NROWS, ND, ND);
    gemm_mma<<<gg, 256, GSMEM>>>(X, Wk_w, Wk_b, pK, NROWS, ND, ND);
    gemm_mma<<<gg, 256, GSMEM>>>(X, Wv_w, Wv_b, pV, NROWS, ND, ND);
    beta_kernel<<<NROWS / 8, 256>>>();
    prep_kernel<<<NB * 64, 256>>>();
    cudaFuncSetAttribute(scan_kernel, cudaFuncAttributeMaxDynamicSharedMemorySize, SCAN_SMEM);
    scan_kernel<<<dim3(32, NB), 256, SCAN_SMEM>>>();
    gemm_mma<<<gg, 256, GSMEM>>>(pO, Wo_w, Wo_b, out, NROWS, ND, ND);
}

// round 5
// speedup vs baseline: 2.0525x; 2.0525x over previous
#include <cuda_runtime.h>
#include <cuda_bf16.h>
#include <cstdint>
#include <cstddef>

#define NB 8
#define NL 4096
#define ND 1024
#define NROWS (NB*NL)   // 32768

// ---- scratch (device globals; no allocation allowed) ----
__device__ float g_Q[(size_t)NROWS * ND];
__device__ float g_K[(size_t)NROWS * ND];
__device__ float g_V[(size_t)NROWS * ND];    // becomes U (=T@Vb) in place
__device__ float g_W[(size_t)NROWS * ND];    // W = T@Kb (row-major)
__device__ float g_O[(size_t)NROWS * ND];
__device__ float g_Kt[(size_t)NROWS * ND];   // K^T per chunk: [b*64+n][kdim][64]
__device__ float g_beta[NROWS];
__device__ float g_A[(size_t)NB * 64 * 64 * 64];

__device__ __forceinline__ uint32_t f2tf32(float x) {
    uint32_t r;
    asm("cvt.rna.tf32.f32 %0, %1;" : "=r"(r) : "f"(x));
    return r;
}
// split fp32 into tf32 hi + tf32 lo (x ~= hi + lo)
__device__ __forceinline__ void tsplit(float x, uint32_t& h, uint32_t& l) {
    h = f2tf32(x);
    l = f2tf32(x - __uint_as_float(h));
}
__device__ __forceinline__ unsigned short bf16bits(float x) {
    return __bfloat16_as_ushort(__float2bfloat16(x));
}
__device__ __forceinline__ float bf16f(unsigned short u) {
    return __bfloat162float(__ushort_as_bfloat16(u));
}

#define MMA_TF32(d, a, b0, b1) \
    asm volatile("mma.sync.aligned.m16n8k8.row.col.f32.tf32.tf32.f32 " \
        "{%0,%1,%2,%3}, {%4,%5,%6,%7}, {%8,%9}, {%0,%1,%2,%3};" \
        : "+f"((d)[0]), "+f"((d)[1]), "+f"((d)[2]), "+f"((d)[3]) \
        : "r"((a)[0]), "r"((a)[1]), "r"((a)[2]), "r"((a)[3]), "r"(b0), "r"(b1))

// =====================================================================
// tf32 mma.sync GEMM: C(MxN) = A(MxK) @ W(NxK)^T + bias(N)   (as R3)
// =====================================================================
#define GPITCH 36
#define GASZ   (128 * GPITCH)
#define GSMEM  (4 * GASZ * 4)

__global__ void __launch_bounds__(256, 1) gemm_mma(
    const float* __restrict__ A, const float* __restrict__ Wm,
    const float* __restrict__ bias, float* __restrict__ C,
    int M, int N, int K)
{
    extern __shared__ uint32_t smg[];
    const int t    = threadIdx.x;
    const int wid  = t >> 5;
    const int lane = t & 31;
    const int wm   = wid & 1;
    const int wn   = wid >> 1;
    const int m0   = blockIdx.y * 128;
    const int n0   = blockIdx.x * 128;
    const int lr   = lane >> 2;
    const int lc   = lane & 3;

    const float* Ap = A  + (size_t)m0 * K;
    const float* Bp = Wm + (size_t)n0 * K;

    float acc[4][4][4];
#pragma unroll
    for (int i = 0; i < 4; i++)
#pragma unroll
        for (int j = 0; j < 4; j++)
#pragma unroll
            for (int x = 0; x < 4; x++) acc[i][j][x] = 0.f;

#pragma unroll
    for (int i = 0; i < 4; i++) {
        int idx = t + i * 256;
        int r = idx >> 3, c4 = idx & 7;
        float4 va = *(const float4*)(Ap + (size_t)r * K + c4 * 4);
        uint32_t* dst = &smg[r * GPITCH + c4 * 4];
        dst[0] = f2tf32(va.x); dst[1] = f2tf32(va.y);
        dst[2] = f2tf32(va.z); dst[3] = f2tf32(va.w);
        float4 vb = *(const float4*)(Bp + (size_t)r * K + c4 * 4);
        uint32_t* dstb = &smg[GASZ + r * GPITCH + c4 * 4];
        dstb[0] = f2tf32(vb.x); dstb[1] = f2tf32(vb.y);
        dstb[2] = f2tf32(vb.z); dstb[3] = f2tf32(vb.w);
    }
    __syncthreads();

    const int nkt = K >> 5;
    for (int kt = 0; kt < nkt; kt++) {
        const int cur = kt & 1;
        float4 ra[4], rb[4];
        if (kt + 1 < nkt) {
            const int ko = (kt + 1) * 32;
#pragma unroll
            for (int i = 0; i < 4; i++) {
                int idx = t + i * 256;
                int r = idx >> 3, c4 = idx & 7;
                ra[i] = *(const float4*)(Ap + (size_t)r * K + ko + c4 * 4);
                rb[i] = *(const float4*)(Bp + (size_t)r * K + ko + c4 * 4);
            }
        }
        const uint32_t* As = smg + cur * 2 * GASZ;
        const uint32_t* Bs = As + GASZ;
#pragma unroll
        for (int k8 = 0; k8 < 4; k8++) {
            const int kb = k8 * 8 + lc;
            uint32_t af[4][4], bf[4][2];
#pragma unroll
            for (int mt = 0; mt < 4; mt++) {
                int r = wm * 64 + mt * 16 + lr;
                af[mt][0] = As[r * GPITCH + kb];
                af[mt][1] = As[(r + 8) * GPITCH + kb];
                af[mt][2] = As[r * GPITCH + kb + 4];
                af[mt][3] = As[(r + 8) * GPITCH + kb + 4];
            }
#pragma unroll
            for (int nt = 0; nt < 4; nt++) {
                int n = wn * 32 + nt * 8 + lr;
                bf[nt][0] = Bs[n * GPITCH + kb];
                bf[nt][1] = Bs[n * GPITCH + kb + 4];
            }
#pragma unroll
            for (int mt = 0; mt < 4; mt++)
#pragma unroll
                for (int nt = 0; nt < 4; nt++)
                    MMA_TF32(acc[mt][nt], af[mt], bf[nt][0], bf[nt][1]);
        }
        if (kt + 1 < nkt) {
            uint32_t* dA = smg + (1 - cur) * 2 * GASZ;
            uint32_t* dB = dA + GASZ;
#pragma unroll
            for (int i = 0; i < 4; i++) {
                int idx = t + i * 256;
                int r = idx >> 3, c4 = idx & 7;
                uint32_t* da = &dA[r * GPITCH + c4 * 4];
                da[0] = f2tf32(ra[i].x); da[1] = f2tf32(ra[i].y);
                da[2] = f2tf32(ra[i].z); da[3] = f2tf32(ra[i].w);
                uint32_t* db = &dB[r * GPITCH + c4 * 4];
                db[0] = f2tf32(rb[i].x); db[1] = f2tf32(rb[i].y);
                db[2] = f2tf32(rb[i].z); db[3] = f2tf32(rb[i].w);
            }
        }
        __syncthreads();
    }

#pragma unroll
    for (int mt = 0; mt < 4; mt++) {
        int r = m0 + wm * 64 + mt * 16 + lr;
#pragma unroll
        for (int nt = 0; nt < 4; nt++) {
            int c = n0 + wn * 32 + nt * 8 + 2 * lc;
            float2 bv = *(const float2*)&bias[c];
            float2 o0, o1;
            o0.x = acc[mt][nt][0] + bv.x; o0.y = acc[mt][nt][1] + bv.y;
            o1.x = acc[mt][nt][2] + bv.x; o1.y = acc[mt][nt][3] + bv.y;
            *(float2*)&C[(size_t)r * N + c]       = o0;
            *(float2*)&C[(size_t)(r + 8) * N + c] = o1;
        }
    }
}

// =====================================================================
// beta[row] = 1 / (||K_row||^2 + 1e-6)
// =====================================================================
__global__ void __launch_bounds__(256) beta_kernel()
{
    int row  = blockIdx.x * 8 + (threadIdx.x >> 5);
    int lane = threadIdx.x & 31;
    const float* p = g_K + (size_t)row * ND;
    float s = 0.f;
#pragma unroll
    for (int i = 0; i < 8; i++) {
        float4 v = *(const float4*)&p[lane * 4 + i * 128];
        s += v.x * v.x + v.y * v.y + v.z * v.z + v.w * v.w;
    }
#pragma unroll
    for (int o = 16; o; o >>= 1) s += __shfl_xor_sync(0xffffffffu, s, o);
    if (lane == 0) g_beta[row] = 1.f / (s + 1e-6f);
}

// =====================================================================
// prep: per (batch, chunk) block; writes A, U (g_V), W (g_W), K^T (g_Kt)
// =====================================================================
#define PPAD 35
__global__ void __launch_bounds__(256) prep_kernel()
{
    __shared__ float sA[64 * PPAD];
    __shared__ float sB[64 * PPAD];
    __shared__ float T_s[64 * 64];
    __shared__ float rowtmp[64];
    __shared__ float beta_s[64];

    const int t  = threadIdx.x;
    const int bc = blockIdx.x;
    const size_t row0 = (size_t)(bc >> 6) * NL + (size_t)(bc & 63) * 64;
    const size_t tb   = (size_t)bc * 65536;

    if (t < 64) beta_s[t] = g_beta[row0 + t];
    __syncthreads();

    const int i0  = (t >> 4) * 4;
    const int j0  = (t & 15) * 4;
    const int lkk = t & 31, ljr = t >> 5;
    const int tj  = t & 63;
    const int tk0 = (t >> 6) * 8;

    float ga[4][4], qa[4][4];
#pragma unroll
    for (int a = 0; a < 4; a++)
#pragma unroll
        for (int b = 0; b < 4; b++) { ga[a][b] = 0.f; qa[a][b] = 0.f; }

    for (int k0 = 0; k0 < ND; k0 += 32) {
#pragma unroll
        for (int h = 0; h < 8; h++) {
            int j = ljr + h * 8;
            sA[j * PPAD + lkk] = g_K[(row0 + j) * ND + k0 + lkk];
            sB[j * PPAD + lkk] = g_Q[(row0 + j) * ND + k0 + lkk];
        }
        __syncthreads();
        // write K^T tile (coalesced)
#pragma unroll
        for (int h = 0; h < 8; h++) {
            int kk = tk0 + h;
            g_Kt[tb + (size_t)(k0 + kk) * 64 + tj] = sA[tj * PPAD + kk];
        }
#pragma unroll
        for (int kk = 0; kk < 32; kk++) {
            float ki[4], kj[4], qi[4];
#pragma unroll
            for (int a = 0; a < 4; a++) {
                ki[a] = sA[(i0 + a) * PPAD + kk];
                qi[a] = sB[(i0 + a) * PPAD + kk];
                kj[a] = sA[(j0 + a) * PPAD + kk];
            }
#pragma unroll
            for (int a = 0; a < 4; a++)
#pragma unroll
                for (int b = 0; b < 4; b++) {
                    ga[a][b] += ki[a] * kj[b];
                    qa[a][b] += qi[a] * kj[b];
                }
        }
        __syncthreads();
    }

    float* Aout = g_A + (size_t)bc * 4096;
#pragma unroll
    for (int a = 0; a < 4; a++)
#pragma unroll
        for (int b = 0; b < 4; b++) {
            int i = i0 + a, j = j0 + b;
            T_s[i * 64 + j]  = (j < i) ? (-beta_s[i] * ga[a][b]) : 0.f;
            Aout[i * 64 + j] = (j <= i) ? qa[a][b] : 0.f;
        }
    __syncthreads();

    for (int i = 1; i < 64; i++) {
        if (t < i) rowtmp[t] = T_s[i * 64 + t];
        __syncthreads();
        if (t < i) {
            float s = 0.f;
            for (int j = t + 1; j < i; j++) s += rowtmp[j] * T_s[j * 64 + t];
            T_s[i * 64 + t] += s;
        }
        __syncthreads();
    }
    if (t < 64) T_s[t * 64 + t] += 1.f;
    __syncthreads();

    const int ip = (t >> 4) * 4;
    const int dp = (t & 15) * 2;
    for (int d0 = 0; d0 < ND; d0 += 32) {
#pragma unroll
        for (int h = 0; h < 8; h++) {
            int j = ljr + h * 8;
            float bj = beta_s[j];
            sA[j * PPAD + lkk] = g_K[(row0 + j) * ND + d0 + lkk] * bj;
            sB[j * PPAD + lkk] = g_V[(row0 + j) * ND + d0 + lkk] * bj;
        }
        __syncthreads();
        float wv[4][2], uv[4][2];
#pragma unroll
        for (int a = 0; a < 4; a++) { wv[a][0] = wv[a][1] = 0.f; uv[a][0] = uv[a][1] = 0.f; }
#pragma unroll
        for (int j = 0; j < 64; j++) {
            float kb0 = sA[j * PPAD + dp], kb1 = sA[j * PPAD + dp + 1];
            float vb0 = sB[j * PPAD + dp], vb1 = sB[j * PPAD + dp + 1];
#pragma unroll
            for (int a = 0; a < 4; a++) {
                float tv = T_s[(ip + a) * 64 + j];
                wv[a][0] += tv * kb0; wv[a][1] += tv * kb1;
                uv[a][0] += tv * vb0; uv[a][1] += tv * vb1;
            }
        }
#pragma unroll
        for (int a = 0; a < 4; a++) {
            size_t off = (row0 + ip + a) * ND + d0 + dp;
            *(float2*)&g_W[off] = make_float2(wv[a][0], wv[a][1]);
            *(float2*)&g_V[off] = make_float2(uv[a][0], uv[a][1]);
        }
        __syncthreads();
    }
}

// =====================================================================
// scan (tensor, 3xTF32): grid (32 colblocks, 8 batches), 256 thr.
// S^T resident in smem as hi(fp32-tf32)/lo(bf16): [32 cols][1024 kdim].
// phase b: warps 0-3: u = U0 - W@S ; warps 4-7: qs = Q@S  (MMA, A from gmem)
// phase c: warps 4-7: O = A_chunk@u + qs (qs stays in accumulators)
// phase d: all warps: S += (u^T @ K^T)^T via MMA on g_Kt, resplit hi/lo
// =====================================================================
#define SHP 1028   // St_hi pitch (floats); 1028%32=4 -> conflict-free frags
#define SLP 1032   // St_lo pitch (uint16)
#define UTP 68     // u_t pitch
#define OFF_SL 131584
#define OFF_UH 197632
#define OFF_UL 206336
#define SCAN_SMEM2 210688

__global__ void __launch_bounds__(256, 1) scan_tc()
{
    extern __shared__ char smc[];
    float*          Sh = (float*)smc;                       // [32][1028]
    unsigned short* Sl = (unsigned short*)(smc + OFF_SL);   // [32][1032]
    float*          Uh = (float*)(smc + OFF_UH);            // [32][68]
    unsigned short* Ul = (unsigned short*)(smc + OFF_UL);   // [32][68]

    const int t    = threadIdx.x;
    const int lane = t & 31;
    const int wid  = t >> 5;
    const int lr   = lane >> 2;
    const int lc   = lane & 3;
    const int b    = blockIdx.y;
    const int cb0  = blockIdx.x * 32;

    for (int i = t; i < 32 * SHP; i += 256) Sh[i] = 0.f;
    for (int i = t; i < 32 * SLP; i += 256) Sl[i] = 0;
    __syncthreads();

    const int  bm  = (wid & 3) * 16;   // phase b/c m-tile base
    const bool isQ = (wid >= 4);
    const int  dm  = (wid & 1) * 16;   // phase d c-row base
    const int  dn  = (wid >> 1) * 256; // phase d kdim base

    for (int n = 0; n < 64; n++) {
        const size_t row0  = (size_t)b * NL + (size_t)n * 64;
        const size_t cbase = (size_t)b * 64 + n;

        // ---------------- phase b ----------------
        float acc[4][4];
        if (!isQ) {
            const size_t rr = row0 + bm + lr;
#pragma unroll
            for (int nt = 0; nt < 4; nt++) {
                int cc = cb0 + nt * 8 + 2 * lc;
                acc[nt][0] = g_V[rr * ND + cc];
                acc[nt][1] = g_V[rr * ND + cc + 1];
                acc[nt][2] = g_V[(rr + 8) * ND + cc];
                acc[nt][3] = g_V[(rr + 8) * ND + cc + 1];
            }
        } else {
#pragma unroll
            for (int nt = 0; nt < 4; nt++)
#pragma unroll
                for (int x = 0; x < 4; x++) acc[nt][x] = 0.f;
        }
        {
            const float* M   = isQ ? g_Q : g_W;
            const float  sgn = isQ ? 1.f : -1.f;
            const float* Mr0 = M + (row0 + bm + lr) * ND;
            const float* Mr8 = Mr0 + 8 * ND;
#pragma unroll 2
            for (int k8 = 0; k8 < 1024; k8 += 8) {
                float w0 = sgn * Mr0[k8 + lc];
                float w1 = sgn * Mr8[k8 + lc];
                float w2 = sgn * Mr0[k8 + lc + 4];
                float w3 = sgn * Mr8[k8 + lc + 4];
                uint32_t ah[4], al[4];
                tsplit(w0, ah[0], al[0]); tsplit(w1, ah[1], al[1]);
                tsplit(w2, ah[2], al[2]); tsplit(w3, ah[3], al[3]);
#pragma unroll
                for (int nt = 0; nt < 4; nt++) {
                    int nr = nt * 8 + lr;
                    uint32_t bh0 = __float_as_uint(Sh[nr * SHP + k8 + lc]);
                    uint32_t bh1 = __float_as_uint(Sh[nr * SHP + k8 + lc + 4]);
                    uint32_t bl0 = __float_as_uint(bf16f(Sl[nr * SLP + k8 + lc]));
                    uint32_t bl1 = __float_as_uint(bf16f(Sl[nr * SLP + k8 + lc + 4]));
                    MMA_TF32(acc[nt], ah, bh0, bh1);
                    MMA_TF32(acc[nt], ah, bl0, bl1);
                    MMA_TF32(acc[nt], al, bh0, bh1);
                }
            }
        }
        // u-warps: write u^T (hi/lo) to smem
        if (!isQ) {
#pragma unroll
            for (int nt = 0; nt < 4; nt++) {
                int c0 = nt * 8 + 2 * lc;
                int j0 = bm + lr;
#pragma unroll
                for (int x = 0; x < 4; x++) {
                    int cc = c0 + (x & 1);
                    int jj = j0 + (x >> 1) * 8;
                    float v  = acc[nt][x];
                    uint32_t h = f2tf32(v);
                    float hf = __uint_as_float(h);
                    Uh[cc * UTP + jj] = hf;
                    Ul[cc * UTP + jj] = bf16bits(v - hf);
                }
            }
        }
        __syncthreads();

        // ---------------- phase c (warps 4-7): O = A@u + qs ----------------
        if (isQ) {
            const float* Ab = g_A + cbase * 4096;
#pragma unroll
            for (int j8 = 0; j8 < 64; j8 += 8) {
                float a0 = Ab[(bm + lr) * 64 + j8 + lc];
                float a1 = Ab[(bm + lr + 8) * 64 + j8 + lc];
                float a2 = Ab[(bm + lr) * 64 + j8 + lc + 4];
                float a3 = Ab[(bm + lr + 8) * 64 + j8 + lc + 4];
                uint32_t ah[4], al[4];
                tsplit(a0, ah[0], al[0]); tsplit(a1, ah[1], al[1]);
                tsplit(a2, ah[2], al[2]); tsplit(a3, ah[3], al[3]);
#pragma unroll
                for (int nt = 0; nt < 4; nt++) {
                    int nr = nt * 8 + lr;
                    uint32_t bh0 = __float_as_uint(Uh[nr * UTP + j8 + lc]);
                    uint32_t bh1 = __float_as_uint(Uh[nr * UTP + j8 + lc + 4]);
                    uint32_t bl0 = __float_as_uint(bf16f(Ul[nr * UTP + j8 + lc]));
                    uint32_t bl1 = __float_as_uint(bf16f(Ul[nr * UTP + j8 + lc + 4]));
                    MMA_TF32(acc[nt], ah, bh0, bh1);
                    MMA_TF32(acc[nt], ah, bl0, bl1);
                    MMA_TF32(acc[nt], al, bh0, bh1);
                }
            }
            const size_t rr = row0 + bm + lr;
#pragma unroll
            for (int nt = 0; nt < 4; nt++) {
                int cc = cb0 + nt * 8 + 2 * lc;
                g_O[rr * ND + cc]           = acc[nt][0];
                g_O[rr * ND + cc + 1]       = acc[nt][1];
                g_O[(rr + 8) * ND + cc]     = acc[nt][2];
                g_O[(rr + 8) * ND + cc + 1] = acc[nt][3];
            }
        }

        // ---------------- phase d: S += K^T @ u (as ΔS^T = u^T@K^T) --------
        {
            const float* Ktb = g_Kt + cbase * 65536;
            for (int sb = 0; sb < 4; sb++) {
                const int kb0 = dn + sb * 64;
                float dacc[8][4];
#pragma unroll
                for (int i = 0; i < 8; i++)
#pragma unroll
                    for (int x = 0; x < 4; x++) dacc[i][x] = 0.f;
#pragma unroll
                for (int j8 = 0; j8 < 64; j8 += 8) {
                    uint32_t ah[4], al[4];
                    {
                        int r0i = (dm + lr) * UTP + j8 + lc;
                        int r8i = (dm + lr + 8) * UTP + j8 + lc;
                        ah[0] = __float_as_uint(Uh[r0i]);
                        ah[1] = __float_as_uint(Uh[r8i]);
                        ah[2] = __float_as_uint(Uh[r0i + 4]);
                        ah[3] = __float_as_uint(Uh[r8i + 4]);
                        al[0] = __float_as_uint(bf16f(Ul[r0i]));
                        al[1] = __float_as_uint(bf16f(Ul[r8i]));
                        al[2] = __float_as_uint(bf16f(Ul[r0i + 4]));
                        al[3] = __float_as_uint(bf16f(Ul[r8i + 4]));
                    }
#pragma unroll
                    for (int nt = 0; nt < 8; nt++) {
                        int nr = kb0 + nt * 8 + lr;
                        float b0f = Ktb[nr * 64 + j8 + lc];
                        float b1f = Ktb[nr * 64 + j8 + lc + 4];
                        uint32_t bh0, bl0, bh1, bl1;
                        tsplit(b0f, bh0, bl0);
                        tsplit(b1f, bh1, bl1);
                        MMA_TF32(dacc[nt], ah, bh0, bh1);
                        MMA_TF32(dacc[nt], ah, bl0, bl1);
                        MMA_TF32(dacc[nt], al, bh0, bh1);
                    }
                }
                // update S^T hi/lo
#pragma unroll
                for (int nt = 0; nt < 8; nt++) {
                    int kk = kb0 + nt * 8 + 2 * lc;
#pragma unroll
                    for (int x = 0; x < 4; x++) {
                        int cc = dm + lr + (x >> 1) * 8;
                        int kx = kk + (x & 1);
                        int hi_i = cc * SHP + kx;
                        int lo_i = cc * SLP + kx;
                        float s = Sh[hi_i] + bf16f(Sl[lo_i]) + dacc[nt][x];
                        uint32_t h = f2tf32(s);
                        float hf = __uint_as_float(h);
                        Sh[hi_i] = hf;
                        Sl[lo_i] = bf16bits(s - hf);
                    }
                }
            }
        }
        __syncthreads();
    }
}

// =====================================================================
extern "C" void kernel_launch(void* const* d_in, const int* in_sizes, int n_in,
                              void* d_out, int out_size)
{
    int base = 1;
    if (n_in >= 10 && in_sizes[1] == 1) base = 2;
    const float* X    = (const float*)d_in[0];
    const float* Wq_w = (const float*)d_in[base + 0];
    const float* Wq_b = (const float*)d_in[base + 1];
    const float* Wk_w = (const float*)d_in[base + 2];
    const float* Wk_b = (const float*)d_in[base + 3];
    const float* Wv_w = (const float*)d_in[base + 4];
    const float* Wv_b = (const float*)d_in[base + 5];
    const float* Wo_w = (const float*)d_in[base + 6];
    const float* Wo_b = (const float*)d_in[base + 7];
    float* out = (float*)d_out;

    float *pQ, *pK, *pV, *pO;
    cudaGetSymbolAddress((void**)&pQ, g_Q);
    cudaGetSymbolAddress((void**)&pK, g_K);
    cudaGetSymbolAddress((void**)&pV, g_V);
    cudaGetSymbolAddress((void**)&pO, g_O);

    cudaFuncSetAttribute(gemm_mma, cudaFuncAttributeMaxDynamicSharedMemorySize, GSMEM);
    dim3 gg(ND / 128, NROWS / 128);
    gemm_mma<<<gg, 256, GSMEM>>>(X, Wq_w, Wq_b, pQ, NROWS, ND, ND);
    gemm_mma<<<gg, 256, GSMEM>>>(X, Wk_w, Wk_b, pK, NROWS, ND, ND);
    gemm_mma<<<gg, 256, GSMEM>>>(X, Wv_w, Wv_b, pV, NROWS, ND, ND);
    beta_kernel<<<NROWS / 8, 256>>>();
    prep_kernel<<<NB * 64, 256>>>();
    cudaFuncSetAttribute(scan_tc, cudaFuncAttributeMaxDynamicSharedMemorySize, SCAN_SMEM2);
    scan_tc<<<dim3(32, NB), 256, SCAN_SMEM2>>>();
    gemm_mma<<<gg, 256, GSMEM>>>(pO, Wo_w, Wo_b, out, NROWS, ND, ND);
}